// round 1
// baseline (speedup 1.0000x reference)
#include <cuda_runtime.h>
#include <math.h>

#define Bn 8
#define Nn 1024
#define Dn 1024
#define Hn 4096
#define En 16
#define CAP 80

// Scratch for the intermediate hidden activations: 8 * 80 * 4096 * 4B = 10.5 MB
__device__ float g_hidden[(size_t)Bn * CAP * Hn];

__device__ __forceinline__ float gelu_exact(float x) {
    // gelu(x) = 0.5 * x * (1 + erf(x / sqrt(2)))  (approximate=False)
    return 0.5f * x * (1.0f + erff(x * 0.70710678118654752440f));
}

// ---------------------------------------------------------------------------
// GEMM1 + GELU: hidden[b] = gelu(X_b @ W1[e_b])
//   X_b: [80, 1024] (tokens 0..79 of sample b), W1[e]: [1024, 4096]
// Block tile: 80(M) x 128(N), BK=16. 128 threads (tx=16, ty=8), TM=10, TN=8.
// Grid: (Hn/128, Bn)
// ---------------------------------------------------------------------------
__global__ __launch_bounds__(128) void gemm1_kernel(
    const float* __restrict__ inputs, const int* __restrict__ y,
    const float* __restrict__ w1)
{
    const int b = blockIdx.y;
    const int e = y[b] % En;   // y in [0, 345), nonnegative
    const float* __restrict__ X = inputs + (size_t)b * Nn * Dn;
    const float* __restrict__ W = w1 + (size_t)e * Dn * Hn;
    float* __restrict__ Hb = g_hidden + (size_t)b * CAP * Hn;
    const int n0 = blockIdx.x * 128;
    const int tid = threadIdx.x;
    const int tx = tid & 15;   // column group 0..15
    const int ty = tid >> 4;   // row group 0..7

    __shared__ float Xs[16][81];    // [k][m], padded to kill store conflicts
    __shared__ float Ws[16][128];   // [k][n]

    float acc[10][8];
    #pragma unroll
    for (int i = 0; i < 10; i++)
        #pragma unroll
        for (int j = 0; j < 8; j++) acc[i][j] = 0.0f;

    for (int k0 = 0; k0 < Dn; k0 += 16) {
        // Load X tile: 80 rows x 16 k  (1280 elems, 10 per thread)
        #pragma unroll
        for (int i = 0; i < 10; i++) {
            int idx = tid + i * 128;
            int k = idx & 15;
            int m = idx >> 4;
            Xs[k][m] = X[(size_t)m * Dn + (k0 + k)];
        }
        // Load W tile: 16 k x 128 n  (512 float4, 4 per thread, coalesced)
        #pragma unroll
        for (int i = 0; i < 4; i++) {
            int idx4 = tid + i * 128;
            int n4 = idx4 & 31;
            int k = idx4 >> 5;
            float4 v = *reinterpret_cast<const float4*>(
                &W[(size_t)(k0 + k) * Hn + n0 + n4 * 4]);
            *reinterpret_cast<float4*>(&Ws[k][n4 * 4]) = v;
        }
        __syncthreads();

        #pragma unroll
        for (int kk = 0; kk < 16; kk++) {
            float xv[10], wv[8];
            #pragma unroll
            for (int i = 0; i < 10; i++) xv[i] = Xs[kk][ty * 10 + i];   // 2-way bcast
            #pragma unroll
            for (int j = 0; j < 8; j++) wv[j] = Ws[kk][tx + 16 * j];    // conflict-free
            #pragma unroll
            for (int i = 0; i < 10; i++)
                #pragma unroll
                for (int j = 0; j < 8; j++)
                    acc[i][j] = fmaf(xv[i], wv[j], acc[i][j]);
        }
        __syncthreads();
    }

    #pragma unroll
    for (int i = 0; i < 10; i++) {
        int m = ty * 10 + i;
        #pragma unroll
        for (int j = 0; j < 8; j++) {
            Hb[(size_t)m * Hn + n0 + tx + 16 * j] = gelu_exact(acc[i][j]);
        }
    }
}

// ---------------------------------------------------------------------------
// GEMM2 (split-K=4): out[b, 0:80, :] += hidden[b] @ W2[e_b]
//   hidden: [80, 4096], W2[e]: [4096, 1024]
// Block tile: 80(M) x 64(N), BK=16. 128 threads, TM=10, TN=4.
// Grid: (Dn/64, Bn, 4). Output pre-zeroed; partials via atomicAdd.
// ---------------------------------------------------------------------------
__global__ __launch_bounds__(128) void gemm2_kernel(
    const int* __restrict__ y, const float* __restrict__ w2,
    float* __restrict__ out)
{
    const int b = blockIdx.y;
    const int e = y[b] % En;
    const float* __restrict__ Hb = g_hidden + (size_t)b * CAP * Hn;
    const float* __restrict__ W = w2 + (size_t)e * Hn * Dn;
    float* __restrict__ Ob = out + (size_t)b * Nn * Dn;
    const int n0 = blockIdx.x * 64;
    const int kbase = blockIdx.z * (Hn / 4);
    const int kend = kbase + (Hn / 4);
    const int tid = threadIdx.x;
    const int tx = tid & 15;
    const int ty = tid >> 4;

    __shared__ float Xs[16][81];
    __shared__ float Ws[16][64];

    float acc[10][4];
    #pragma unroll
    for (int i = 0; i < 10; i++)
        #pragma unroll
        for (int j = 0; j < 4; j++) acc[i][j] = 0.0f;

    for (int k0 = kbase; k0 < kend; k0 += 16) {
        #pragma unroll
        for (int i = 0; i < 10; i++) {
            int idx = tid + i * 128;
            int k = idx & 15;
            int m = idx >> 4;
            Xs[k][m] = Hb[(size_t)m * Hn + (k0 + k)];
        }
        // 16 k x 64 n = 256 float4, 2 per thread
        #pragma unroll
        for (int i = 0; i < 2; i++) {
            int idx4 = tid + i * 128;
            int n4 = idx4 & 15;
            int k = idx4 >> 4;
            float4 v = *reinterpret_cast<const float4*>(
                &W[(size_t)(k0 + k) * Dn + n0 + n4 * 4]);
            *reinterpret_cast<float4*>(&Ws[k][n4 * 4]) = v;
        }
        __syncthreads();

        #pragma unroll
        for (int kk = 0; kk < 16; kk++) {
            float xv[10], wv[4];
            #pragma unroll
            for (int i = 0; i < 10; i++) xv[i] = Xs[kk][ty * 10 + i];
            #pragma unroll
            for (int j = 0; j < 4; j++) wv[j] = Ws[kk][tx + 16 * j];
            #pragma unroll
            for (int i = 0; i < 10; i++)
                #pragma unroll
                for (int j = 0; j < 4; j++)
                    acc[i][j] = fmaf(xv[i], wv[j], acc[i][j]);
        }
        __syncthreads();
    }

    #pragma unroll
    for (int i = 0; i < 10; i++) {
        int m = ty * 10 + i;
        #pragma unroll
        for (int j = 0; j < 4; j++) {
            atomicAdd(&Ob[(size_t)m * Dn + n0 + tx + 16 * j], acc[i][j]);
        }
    }
}

extern "C" void kernel_launch(void* const* d_in, const int* in_sizes, int n_in,
                              void* d_out, int out_size) {
    const float* inputs = (const float*)d_in[0];   // (8, 1024, 1024) f32
    const int*   y      = (const int*)d_in[1];     // (8,) i32
    const float* w1     = (const float*)d_in[2];   // (16, 1024, 4096) f32
    const float* w2     = (const float*)d_in[3];   // (16, 4096, 1024) f32
    float* out = (float*)d_out;                    // (8, 1024, 1024) f32

    // Output is poisoned; rows >= CAP must be exactly zero, and GEMM2
    // accumulates with atomics, so zero everything first (memset node).
    cudaMemsetAsync(out, 0, (size_t)out_size * sizeof(float), 0);

    dim3 g1(Hn / 128, Bn);
    gemm1_kernel<<<g1, 128>>>(inputs, y, w1);

    dim3 g2(Dn / 64, Bn, 4);
    gemm2_kernel<<<g2, 128>>>(y, w2, out);
}

// round 2
// speedup vs baseline: 1.0762x; 1.0762x over previous
#include <cuda_runtime.h>
#include <math.h>

#define Bn 8
#define Nn 1024
#define Dn 1024
#define Hn 4096
#define En 16
#define CAP 80
#define SPLITK 4

// Scratch: hidden activations (8*80*4096 f32 = 10.5 MB) and split-K partials
__device__ float g_hidden[(size_t)Bn * CAP * Hn];
__device__ float g_partial[(size_t)SPLITK * Bn * CAP * Dn];

__device__ __forceinline__ float gelu_exact(float x) {
    return 0.5f * x * (1.0f + erff(x * 0.70710678118654752440f));
}

// ---------------------------------------------------------------------------
// Shared GEMM core: C[80 x 256] += A[80 x K] * B[K x 256]
// A is row-major [80 x lda] (lda = K stride), B row-major [K x ldb].
// 320 threads: tx = tid%32 (n, TN=8), tm = tid/32 (0..9, TM=8).
// BK=16, double-buffered smem, register-staged global loads.
// ---------------------------------------------------------------------------

__global__ __launch_bounds__(320) void gemm1_kernel(
    const float* __restrict__ inputs, const int* __restrict__ y,
    const float* __restrict__ w1)
{
    const int b = blockIdx.y;
    const int e = y[b] % En;
    const float* __restrict__ A = inputs + (size_t)b * Nn * Dn;        // [80 x 1024], lda=1024
    const float* __restrict__ Bm = w1 + (size_t)e * Dn * Hn;           // [1024 x 4096], ldb=4096
    float* __restrict__ Hb = g_hidden + (size_t)b * CAP * Hn;
    const int n0 = blockIdx.x * 256;
    const int tid = threadIdx.x;
    const int tx = tid & 31;
    const int tm = tid >> 5;

    __shared__ float Xs[2][16][80];
    __shared__ float Ws[2][16][256];

    // staging index precompute
    const int xm = tid % 80;            // A row
    const int xk4 = tid / 80;           // A k-quad (0..3)

    float acc[8][8];
    #pragma unroll
    for (int i = 0; i < 8; i++)
        #pragma unroll
        for (int j = 0; j < 8; j++) acc[i][j] = 0.0f;

    float4 xreg;
    float4 wreg[4];

    // prologue: tile 0
    {
        const int k0 = 0;
        xreg = *reinterpret_cast<const float4*>(&A[(size_t)xm * Dn + k0 + xk4 * 4]);
        #pragma unroll
        for (int i = 0; i < 4; i++) {
            int widx = tid + i * 320;
            if (widx < 1024) {
                int wk = widx >> 6;
                int wn4 = widx & 63;
                wreg[i] = *reinterpret_cast<const float4*>(
                    &Bm[(size_t)(k0 + wk) * Hn + n0 + wn4 * 4]);
            }
        }
        Xs[0][xk4 * 4 + 0][xm] = xreg.x;
        Xs[0][xk4 * 4 + 1][xm] = xreg.y;
        Xs[0][xk4 * 4 + 2][xm] = xreg.z;
        Xs[0][xk4 * 4 + 3][xm] = xreg.w;
        #pragma unroll
        for (int i = 0; i < 4; i++) {
            int widx = tid + i * 320;
            if (widx < 1024) {
                int wk = widx >> 6;
                int wn4 = widx & 63;
                *reinterpret_cast<float4*>(&Ws[0][wk][wn4 * 4]) = wreg[i];
            }
        }
    }
    __syncthreads();

    int buf = 0;
    const int ITERS = Dn / 16;  // 64
    for (int it = 0; it < ITERS; it++) {
        if (it + 1 < ITERS) {
            const int k0 = (it + 1) * 16;
            xreg = *reinterpret_cast<const float4*>(&A[(size_t)xm * Dn + k0 + xk4 * 4]);
            #pragma unroll
            for (int i = 0; i < 4; i++) {
                int widx = tid + i * 320;
                if (widx < 1024) {
                    int wk = widx >> 6;
                    int wn4 = widx & 63;
                    wreg[i] = *reinterpret_cast<const float4*>(
                        &Bm[(size_t)(k0 + wk) * Hn + n0 + wn4 * 4]);
                }
            }
        }

        #pragma unroll
        for (int kk = 0; kk < 16; kk++) {
            float4 xv0 = *reinterpret_cast<const float4*>(&Xs[buf][kk][tm * 8 + 0]);
            float4 xv1 = *reinterpret_cast<const float4*>(&Xs[buf][kk][tm * 8 + 4]);
            float4 wv0 = *reinterpret_cast<const float4*>(&Ws[buf][kk][tx * 8 + 0]);
            float4 wv1 = *reinterpret_cast<const float4*>(&Ws[buf][kk][tx * 8 + 4]);
            float xv[8] = {xv0.x, xv0.y, xv0.z, xv0.w, xv1.x, xv1.y, xv1.z, xv1.w};
            float wv[8] = {wv0.x, wv0.y, wv0.z, wv0.w, wv1.x, wv1.y, wv1.z, wv1.w};
            #pragma unroll
            for (int i = 0; i < 8; i++)
                #pragma unroll
                for (int j = 0; j < 8; j++)
                    acc[i][j] = fmaf(xv[i], wv[j], acc[i][j]);
        }

        if (it + 1 < ITERS) {
            int nb = buf ^ 1;
            Xs[nb][xk4 * 4 + 0][xm] = xreg.x;
            Xs[nb][xk4 * 4 + 1][xm] = xreg.y;
            Xs[nb][xk4 * 4 + 2][xm] = xreg.z;
            Xs[nb][xk4 * 4 + 3][xm] = xreg.w;
            #pragma unroll
            for (int i = 0; i < 4; i++) {
                int widx = tid + i * 320;
                if (widx < 1024) {
                    int wk = widx >> 6;
                    int wn4 = widx & 63;
                    *reinterpret_cast<float4*>(&Ws[nb][wk][wn4 * 4]) = wreg[i];
                }
            }
            __syncthreads();
            buf = nb;
        }
    }

    // epilogue: gelu + store
    #pragma unroll
    for (int i = 0; i < 8; i++) {
        int m = tm * 8 + i;
        #pragma unroll
        for (int jq = 0; jq < 2; jq++) {
            float4 v;
            v.x = gelu_exact(acc[i][jq * 4 + 0]);
            v.y = gelu_exact(acc[i][jq * 4 + 1]);
            v.z = gelu_exact(acc[i][jq * 4 + 2]);
            v.w = gelu_exact(acc[i][jq * 4 + 3]);
            *reinterpret_cast<float4*>(&Hb[(size_t)m * Hn + n0 + tx * 8 + jq * 4]) = v;
        }
    }
}

__global__ __launch_bounds__(320) void gemm2_kernel(
    const int* __restrict__ y, const float* __restrict__ w2)
{
    const int b = blockIdx.y;
    const int e = y[b] % En;
    const int split = blockIdx.z;
    const float* __restrict__ A = g_hidden + (size_t)b * CAP * Hn;     // [80 x 4096]
    const float* __restrict__ Bm = w2 + (size_t)e * Hn * Dn;           // [4096 x 1024]
    float* __restrict__ P = g_partial + ((size_t)split * Bn + b) * CAP * Dn;
    const int n0 = blockIdx.x * 256;
    const int kbase = split * (Hn / SPLITK);                            // 1024 chunk
    const int tid = threadIdx.x;
    const int tx = tid & 31;
    const int tm = tid >> 5;

    __shared__ float Xs[2][16][80];
    __shared__ float Ws[2][16][256];

    const int xm = tid % 80;
    const int xk4 = tid / 80;

    float acc[8][8];
    #pragma unroll
    for (int i = 0; i < 8; i++)
        #pragma unroll
        for (int j = 0; j < 8; j++) acc[i][j] = 0.0f;

    float4 xreg;
    float4 wreg[4];

    {
        const int k0 = kbase;
        xreg = *reinterpret_cast<const float4*>(&A[(size_t)xm * Hn + k0 + xk4 * 4]);
        #pragma unroll
        for (int i = 0; i < 4; i++) {
            int widx = tid + i * 320;
            if (widx < 1024) {
                int wk = widx >> 6;
                int wn4 = widx & 63;
                wreg[i] = *reinterpret_cast<const float4*>(
                    &Bm[(size_t)(k0 + wk) * Dn + n0 + wn4 * 4]);
            }
        }
        Xs[0][xk4 * 4 + 0][xm] = xreg.x;
        Xs[0][xk4 * 4 + 1][xm] = xreg.y;
        Xs[0][xk4 * 4 + 2][xm] = xreg.z;
        Xs[0][xk4 * 4 + 3][xm] = xreg.w;
        #pragma unroll
        for (int i = 0; i < 4; i++) {
            int widx = tid + i * 320;
            if (widx < 1024) {
                int wk = widx >> 6;
                int wn4 = widx & 63;
                *reinterpret_cast<float4*>(&Ws[0][wk][wn4 * 4]) = wreg[i];
            }
        }
    }
    __syncthreads();

    int buf = 0;
    const int ITERS = (Hn / SPLITK) / 16;  // 64
    for (int it = 0; it < ITERS; it++) {
        if (it + 1 < ITERS) {
            const int k0 = kbase + (it + 1) * 16;
            xreg = *reinterpret_cast<const float4*>(&A[(size_t)xm * Hn + k0 + xk4 * 4]);
            #pragma unroll
            for (int i = 0; i < 4; i++) {
                int widx = tid + i * 320;
                if (widx < 1024) {
                    int wk = widx >> 6;
                    int wn4 = widx & 63;
                    wreg[i] = *reinterpret_cast<const float4*>(
                        &Bm[(size_t)(k0 + wk) * Dn + n0 + wn4 * 4]);
                }
            }
        }

        #pragma unroll
        for (int kk = 0; kk < 16; kk++) {
            float4 xv0 = *reinterpret_cast<const float4*>(&Xs[buf][kk][tm * 8 + 0]);
            float4 xv1 = *reinterpret_cast<const float4*>(&Xs[buf][kk][tm * 8 + 4]);
            float4 wv0 = *reinterpret_cast<const float4*>(&Ws[buf][kk][tx * 8 + 0]);
            float4 wv1 = *reinterpret_cast<const float4*>(&Ws[buf][kk][tx * 8 + 4]);
            float xv[8] = {xv0.x, xv0.y, xv0.z, xv0.w, xv1.x, xv1.y, xv1.z, xv1.w};
            float wv[8] = {wv0.x, wv0.y, wv0.z, wv0.w, wv1.x, wv1.y, wv1.z, wv1.w};
            #pragma unroll
            for (int i = 0; i < 8; i++)
                #pragma unroll
                for (int j = 0; j < 8; j++)
                    acc[i][j] = fmaf(xv[i], wv[j], acc[i][j]);
        }

        if (it + 1 < ITERS) {
            int nb = buf ^ 1;
            Xs[nb][xk4 * 4 + 0][xm] = xreg.x;
            Xs[nb][xk4 * 4 + 1][xm] = xreg.y;
            Xs[nb][xk4 * 4 + 2][xm] = xreg.z;
            Xs[nb][xk4 * 4 + 3][xm] = xreg.w;
            #pragma unroll
            for (int i = 0; i < 4; i++) {
                int widx = tid + i * 320;
                if (widx < 1024) {
                    int wk = widx >> 6;
                    int wn4 = widx & 63;
                    *reinterpret_cast<float4*>(&Ws[nb][wk][wn4 * 4]) = wreg[i];
                }
            }
            __syncthreads();
            buf = nb;
        }
    }

    #pragma unroll
    for (int i = 0; i < 8; i++) {
        int m = tm * 8 + i;
        #pragma unroll
        for (int jq = 0; jq < 2; jq++) {
            float4 v;
            v.x = acc[i][jq * 4 + 0];
            v.y = acc[i][jq * 4 + 1];
            v.z = acc[i][jq * 4 + 2];
            v.w = acc[i][jq * 4 + 3];
            *reinterpret_cast<float4*>(&P[(size_t)m * Dn + n0 + tx * 8 + jq * 4]) = v;
        }
    }
}

// Sum split-K partials into out for tokens < CAP; zero otherwise.
// Covers the whole 8x1024x1024 output (replaces the memset).
__global__ __launch_bounds__(256) void reduce_kernel(float* __restrict__ out)
{
    const size_t idx4 = (size_t)blockIdx.x * blockDim.x + threadIdx.x;  // float4 index
    const size_t total4 = (size_t)Bn * Nn * Dn / 4;                     // 2,097,152
    if (idx4 >= total4) return;
    const int per_b4 = Nn * Dn / 4;            // 262144
    const int b = (int)(idx4 / per_b4);
    const int r = (int)(idx4 % per_b4);
    const int tok = r / (Dn / 4);
    const int d4 = r % (Dn / 4);

    float4 v = make_float4(0.f, 0.f, 0.f, 0.f);
    if (tok < CAP) {
        #pragma unroll
        for (int s = 0; s < SPLITK; s++) {
            const float4 p = *reinterpret_cast<const float4*>(
                &g_partial[(((size_t)s * Bn + b) * CAP + tok) * Dn + d4 * 4]);
            v.x += p.x; v.y += p.y; v.z += p.z; v.w += p.w;
        }
    }
    reinterpret_cast<float4*>(out)[idx4] = v;
}

extern "C" void kernel_launch(void* const* d_in, const int* in_sizes, int n_in,
                              void* d_out, int out_size) {
    const float* inputs = (const float*)d_in[0];   // (8, 1024, 1024) f32
    const int*   y      = (const int*)d_in[1];     // (8,) i32
    const float* w1     = (const float*)d_in[2];   // (16, 1024, 4096) f32
    const float* w2     = (const float*)d_in[3];   // (16, 4096, 1024) f32
    float* out = (float*)d_out;                    // (8, 1024, 1024) f32

    dim3 g1(Hn / 256, Bn);                 // 16 x 8 = 128 blocks
    gemm1_kernel<<<g1, 320>>>(inputs, y, w1);

    dim3 g2(Dn / 256, Bn, SPLITK);         // 4 x 8 x 4 = 128 blocks
    gemm2_kernel<<<g2, 320>>>(y, w2);

    const size_t total4 = (size_t)Bn * Nn * Dn / 4;
    reduce_kernel<<<(unsigned)((total4 + 255) / 256), 256>>>(out);
}

// round 5
// speedup vs baseline: 2.9044x; 2.6988x over previous
#include <cuda_runtime.h>
#include <cstdint>
#include <math.h>

#define Bn 8
#define Nn 1024
#define Dn 1024
#define Hn 4096
#define En 16
#define CAP 80
#define SPLITK 4

#define NT 128      // block tile N
#define KT 32       // block tile K

// smem layout in uint32 units, double-buffered:
//   AH [80][20] (k-pairs, stride 20 for bank spread) = 1600
//   AL [80][20]                                      = 1600
//   BH [16][128] (pair-row p, n ^ 8*(p&3))           = 2048
//   BL [16][128]                                     = 2048
#define APS 20
#define OFF_AH 0
#define OFF_AL 1600
#define OFF_BH 3200
#define OFF_BL 5248
#define TILE_U32 7296
#define SMEM_BYTES (2 * TILE_U32 * 4)   // 58368

__device__ float g_hidden[(size_t)Bn * CAP * Hn];
__device__ float g_partial[(size_t)SPLITK * Bn * CAP * Dn];

__device__ __forceinline__ float gelu_exact(float x) {
    return 0.5f * x * (1.0f + erff(x * 0.70710678118654752440f));
}

// Split two f32 into packed bf16x2 hi (truncated) and lo (rounded residual).
// hi = {trunc16(y) : trunc16(x)}  (x in low half), lo likewise.
__device__ __forceinline__ void split2(float x, float y, uint32_t& hi, uint32_t& lo) {
    uint32_t bx = __float_as_uint(x), by = __float_as_uint(y);
    asm("prmt.b32 %0, %1, %2, 0x7632;" : "=r"(hi) : "r"(bx), "r"(by));
    float lx = x - __uint_as_float(bx & 0xFFFF0000u);
    float ly = y - __uint_as_float(by & 0xFFFF0000u);
    asm("cvt.rn.bf16x2.f32 %0, %1, %2;" : "=r"(lo) : "f"(ly), "f"(lx));
}

__device__ __forceinline__ void mma_bf16(
    float* acc, uint32_t a0, uint32_t a1, uint32_t a2, uint32_t a3,
    uint32_t b0, uint32_t b1)
{
    asm volatile(
        "mma.sync.aligned.m16n8k16.row.col.f32.bf16.bf16.f32 "
        "{%0,%1,%2,%3}, {%4,%5,%6,%7}, {%8,%9}, {%0,%1,%2,%3};"
        : "+f"(acc[0]), "+f"(acc[1]), "+f"(acc[2]), "+f"(acc[3])
        : "r"(a0), "r"(a1), "r"(a2), "r"(a3), "r"(b0), "r"(b1));
}

// ---------------------------------------------------------------------------
// Core: Out[m<80, n0:n0+128] = A[80 x K] * B[K x N] over k in
// [kbase, kbase+ktiles*32). 3-term bf16-split mma.sync, fp32 accum.
// 320 threads = 10 warps (5 M x 2 N), warp tile 16x64.
// ---------------------------------------------------------------------------
template <bool GELU>
__device__ __forceinline__ void gemm_core(
    const float* __restrict__ A, int lda,
    const float* __restrict__ Bg, int ldb,
    int n0, int kbase, int ktiles,
    float* __restrict__ Out, int ldo)
{
    extern __shared__ uint32_t Sm[];
    const int tid = threadIdx.x;
    const int wid = tid >> 5;
    const int lane = tid & 31;
    const int wm = wid >> 1;        // 0..4
    const int wn = wid & 1;         // 0..1
    const int g = lane >> 2;        // 0..7
    const int c = lane & 3;         // 0..3

    // ---- loader mappings ----
    const int a_m = tid >> 2;                 // 0..79
    const int a_seg = tid & 3;                // 0..3 (8 k each)
    const float* a_src = A + (size_t)a_m * lda + a_seg * 8;
    const int a_dst = a_m * APS + a_seg * 4;

    const int b_p0 = tid >> 5;                // unit0: p 0..9? no: tid<320 -> p=tid>>5 in 0..9
    // units: u = tid (0..319) and u = tid + 320 (tid < 192)
    const int u0_p = tid >> 5;                // 0..9
    const int u0_n = (tid & 31) * 4;
    const int u1 = tid + 320;                 // 320..511 for tid<192
    const int u1_p = u1 >> 5;                 // 10..15
    const int u1_n = (u1 & 31) * 4;
    const bool has_u1 = (tid < 192);
    const int b_dst0 = u0_p * 128 + (u0_n ^ (8 * (u0_p & 3)));
    const int b_dst1 = u1_p * 128 + (u1_n ^ (8 * (u1_p & 3)));

    float4 arg0, arg1;                        // A staging (8 f32)
    float4 br00, br01, br10, br11;            // B staging (2 units x 2 rows)

    float acc[8][4];
    #pragma unroll
    for (int j = 0; j < 8; j++)
        #pragma unroll
        for (int i = 0; i < 4; i++) acc[j][i] = 0.0f;

    // ---- helpers as lambdas ----
    auto ldg_tile = [&](int k0) {
        const float* as = a_src + k0;
        arg0 = *reinterpret_cast<const float4*>(as);
        arg1 = *reinterpret_cast<const float4*>(as + 4);
        const float* bs0 = Bg + (size_t)(k0 + 2 * u0_p) * ldb + n0 + u0_n;
        br00 = *reinterpret_cast<const float4*>(bs0);
        br01 = *reinterpret_cast<const float4*>(bs0 + ldb);
        if (has_u1) {
            const float* bs1 = Bg + (size_t)(k0 + 2 * u1_p) * ldb + n0 + u1_n;
            br10 = *reinterpret_cast<const float4*>(bs1);
            br11 = *reinterpret_cast<const float4*>(bs1 + ldb);
        }
    };
    auto sts_tile = [&](int buf) {
        uint32_t* base = Sm + buf * TILE_U32;
        uint32_t h[4], l[4];
        // A: pairs (e0,e1)(e2,e3)(e4,e5)(e6,e7)
        split2(arg0.x, arg0.y, h[0], l[0]);
        split2(arg0.z, arg0.w, h[1], l[1]);
        split2(arg1.x, arg1.y, h[2], l[2]);
        split2(arg1.z, arg1.w, h[3], l[3]);
        *reinterpret_cast<uint4*>(base + OFF_AH + a_dst) = make_uint4(h[0], h[1], h[2], h[3]);
        *reinterpret_cast<uint4*>(base + OFF_AL + a_dst) = make_uint4(l[0], l[1], l[2], l[3]);
        // B unit 0: pair (row 2p low, row 2p+1 high)
        split2(br00.x, br01.x, h[0], l[0]);
        split2(br00.y, br01.y, h[1], l[1]);
        split2(br00.z, br01.z, h[2], l[2]);
        split2(br00.w, br01.w, h[3], l[3]);
        *reinterpret_cast<uint4*>(base + OFF_BH + b_dst0) = make_uint4(h[0], h[1], h[2], h[3]);
        *reinterpret_cast<uint4*>(base + OFF_BL + b_dst0) = make_uint4(l[0], l[1], l[2], l[3]);
        if (has_u1) {
            split2(br10.x, br11.x, h[0], l[0]);
            split2(br10.y, br11.y, h[1], l[1]);
            split2(br10.z, br11.z, h[2], l[2]);
            split2(br10.w, br11.w, h[3], l[3]);
            *reinterpret_cast<uint4*>(base + OFF_BH + b_dst1) = make_uint4(h[0], h[1], h[2], h[3]);
            *reinterpret_cast<uint4*>(base + OFF_BL + b_dst1) = make_uint4(l[0], l[1], l[2], l[3]);
        }
    };

    // ---- prologue ----
    ldg_tile(kbase);
    sts_tile(0);
    if (ktiles > 1) ldg_tile(kbase + KT);
    __syncthreads();

    const int arow0 = (wm * 16 + g) * APS;
    const int arow1 = arow0 + 8 * APS;

    for (int j = 0; j < ktiles; j++) {
        const int buf = j & 1;
        const uint32_t* AH = Sm + buf * TILE_U32 + OFF_AH;
        const uint32_t* AL = Sm + buf * TILE_U32 + OFF_AL;
        const uint32_t* BH = Sm + buf * TILE_U32 + OFF_BH;
        const uint32_t* BL = Sm + buf * TILE_U32 + OFF_BL;

        #pragma unroll
        for (int q = 0; q < 2; q++) {
            const int pa = 8 * q + c;
            uint32_t ah0 = AH[arow0 + pa], ah1 = AH[arow1 + pa];
            uint32_t ah2 = AH[arow0 + pa + 4], ah3 = AH[arow1 + pa + 4];
            uint32_t al0 = AL[arow0 + pa], al1 = AL[arow1 + pa];
            uint32_t al2 = AL[arow0 + pa + 4], al3 = AL[arow1 + pa + 4];
            const int pb0 = (8 * q + c) * 128;
            const int pb1 = (8 * q + c + 4) * 128;
            #pragma unroll
            for (int jf = 0; jf < 8; jf++) {
                const int nn = (wn * 64 + jf * 8 + g) ^ (8 * c);
                uint32_t bh0 = BH[pb0 + nn], bh1 = BH[pb1 + nn];
                uint32_t bl0 = BL[pb0 + nn], bl1 = BL[pb1 + nn];
                mma_bf16(acc[jf], ah0, ah1, ah2, ah3, bh0, bh1);
                mma_bf16(acc[jf], ah0, ah1, ah2, ah3, bl0, bl1);
                mma_bf16(acc[jf], al0, al1, al2, al3, bh0, bh1);
            }
        }

        if (j + 1 < ktiles) {
            sts_tile((j + 1) & 1);
            if (j + 2 < ktiles) ldg_tile(kbase + (j + 2) * KT);
        }
        __syncthreads();
    }

    // ---- epilogue: all rows < 80 by construction ----
    #pragma unroll
    for (int jf = 0; jf < 8; jf++) {
        const int n = n0 + wn * 64 + jf * 8 + 2 * c;
        #pragma unroll
        for (int h = 0; h < 2; h++) {
            const int m = wm * 16 + g + 8 * h;
            float2 v;
            v.x = acc[jf][2 * h + 0];
            v.y = acc[jf][2 * h + 1];
            if (GELU) { v.x = gelu_exact(v.x); v.y = gelu_exact(v.y); }
            *reinterpret_cast<float2*>(&Out[(size_t)m * ldo + n]) = v;
        }
    }
}

__global__ __launch_bounds__(320, 2)
void gemm1_kernel(const float* __restrict__ inputs, const int* __restrict__ y,
                  const float* __restrict__ w1)
{
    const int b = blockIdx.y;
    const int e = y[b] % En;
    gemm_core<true>(inputs + (size_t)b * Nn * Dn, Dn,
                    w1 + (size_t)e * Dn * Hn, Hn,
                    blockIdx.x * NT, 0, Dn / KT,
                    g_hidden + (size_t)b * CAP * Hn, Hn);
}

__global__ __launch_bounds__(320, 2)
void gemm2_kernel(const int* __restrict__ y, const float* __restrict__ w2)
{
    const int b = blockIdx.y;
    const int e = y[b] % En;
    const int split = blockIdx.z;
    gemm_core<false>(g_hidden + (size_t)b * CAP * Hn, Hn,
                     w2 + (size_t)e * Hn * Dn, Dn,
                     blockIdx.x * NT, split * (Hn / SPLITK), (Hn / SPLITK) / KT,
                     g_partial + ((size_t)split * Bn + b) * CAP * Dn, Dn);
}

// Sum split-K partials into out for tokens < CAP; zero otherwise.
__global__ __launch_bounds__(256) void reduce_kernel(float* __restrict__ out)
{
    const size_t idx4 = (size_t)blockIdx.x * blockDim.x + threadIdx.x;
    const size_t total4 = (size_t)Bn * Nn * Dn / 4;
    if (idx4 >= total4) return;
    const int per_b4 = Nn * Dn / 4;
    const int b = (int)(idx4 / per_b4);
    const int r = (int)(idx4 % per_b4);
    const int tok = r / (Dn / 4);
    const int d4 = r % (Dn / 4);

    float4 v = make_float4(0.f, 0.f, 0.f, 0.f);
    if (tok < CAP) {
        #pragma unroll
        for (int s = 0; s < SPLITK; s++) {
            const float4 p = *reinterpret_cast<const float4*>(
                &g_partial[(((size_t)s * Bn + b) * CAP + tok) * Dn + d4 * 4]);
            v.x += p.x; v.y += p.y; v.z += p.z; v.w += p.w;
        }
    }
    reinterpret_cast<float4*>(out)[idx4] = v;
}

extern "C" void kernel_launch(void* const* d_in, const int* in_sizes, int n_in,
                              void* d_out, int out_size) {
    const float* inputs = (const float*)d_in[0];   // (8, 1024, 1024) f32
    const int*   y      = (const int*)d_in[1];     // (8,) i32
    const float* w1     = (const float*)d_in[2];   // (16, 1024, 4096) f32
    const float* w2     = (const float*)d_in[3];   // (16, 4096, 1024) f32
    float* out = (float*)d_out;                    // (8, 1024, 1024) f32

    cudaFuncSetAttribute(gemm1_kernel, cudaFuncAttributeMaxDynamicSharedMemorySize, SMEM_BYTES);
    cudaFuncSetAttribute(gemm2_kernel, cudaFuncAttributeMaxDynamicSharedMemorySize, SMEM_BYTES);

    dim3 g1(Hn / NT, Bn);              // 32 x 8 = 256 CTAs
    gemm1_kernel<<<g1, 320, SMEM_BYTES>>>(inputs, y, w1);

    dim3 g2(Dn / NT, Bn, SPLITK);      // 8 x 8 x 4 = 256 CTAs
    gemm2_kernel<<<g2, 320, SMEM_BYTES>>>(y, w2);

    const size_t total4 = (size_t)Bn * Nn * Dn / 4;
    reduce_kernel<<<(unsigned)((total4 + 255) / 256), 256>>>(out);
}